// round 15
// baseline (speedup 1.0000x reference)
#include <cuda_runtime.h>
#include <cuda_fp16.h>
#include <cstdint>

// FlashAttention B=2,H=16,S=4096,D=64 fp32, non-causal.
// Reference's exact recurrence (block_max variant), BN=128 fixed, in order.
// All-fp16 tensor path, fp32 accumulate; exp2 domain (ex2.approx.f16x2).
// BM=128, 32 rows/warp (groups A/B). Score passes run SEQUENTIALLY per group
// (c regs reused; K fragments reloaded for B) to contain registers; V
// fragments + cp.async stores amortized over all 128 rows -> crossbar cut
// ~30% vs 16-row warps. Quarter-wise exp with HMUL2 correction to the
// 128-block max keeps reference semantics. 96KB smem -> 2 CTAs/SM.

#define SEQ   4096
#define HD    64
#define BM    128
#define BN    128
#define NTHR  128
#define NBLK  (SEQ / BN)
#define SCL2E 0.18033688011112042f   // (1/8)*log2(e)
#define ONES2 0x3C003C00u            // half2(1,1)

#define NTOT  (2 * 16 * SEQ * HD)

__device__ __half g_q[NTOT];
__device__ __half g_k[NTOT];
__device__ __half g_v[NTOT];

// ---------------- converter ----------------
__global__ __launch_bounds__(512)
void cvt_kernel(const float* __restrict__ q,
                const float* __restrict__ k,
                const float* __restrict__ v)
{
    int i = blockIdx.x * blockDim.x + threadIdx.x;
    if (i >= NTOT / 4) return;

    float4 tq = ((const float4*)q)[i];
    __half2 qa = __floats2half2_rn(tq.x * SCL2E, tq.y * SCL2E);
    __half2 qb = __floats2half2_rn(tq.z * SCL2E, tq.w * SCL2E);
    *(uint2*)(g_q + 4 * i) = make_uint2(*(uint32_t*)&qa, *(uint32_t*)&qb);

    float4 tk = ((const float4*)k)[i];
    __half2 ka = __floats2half2_rn(tk.x, tk.y);
    __half2 kb = __floats2half2_rn(tk.z, tk.w);
    *(uint2*)(g_k + 4 * i) = make_uint2(*(uint32_t*)&ka, *(uint32_t*)&kb);

    float4 tv = ((const float4*)v)[i];
    __half2 va = __floats2half2_rn(tv.x, tv.y);
    __half2 vb = __floats2half2_rn(tv.z, tv.w);
    *(uint2*)(g_v + 4 * i) = make_uint2(*(uint32_t*)&va, *(uint32_t*)&vb);
}

// ---------------- smem layout (byte offsets) ----------------
// K slots: 0,16384,32768.  V slots: 49152 + (i%3)*16384.
#define O_K0   0
#define O_V0   49152
#define SMEM_BYTES 98304      // 96KB -> 2 CTAs/SM

__device__ __forceinline__ uint32_t swz(uint32_t row, uint32_t ch)
{
    return (row * 8u + (ch ^ (row & 7u))) * 16u;
}

__device__ __forceinline__ void cp16(uint32_t dst, const void* src)
{
    asm volatile("cp.async.cg.shared.global [%0], [%1], 16;" :: "r"(dst), "l"(src));
}
__device__ __forceinline__ void cp_commit() { asm volatile("cp.async.commit_group;"); }
__device__ __forceinline__ void cp_wait1()  { asm volatile("cp.async.wait_group 1;"); }

__device__ __forceinline__ void ldm_x4(uint32_t a, uint32_t* r)
{
    asm volatile("ldmatrix.sync.aligned.m8n8.x4.shared.b16 {%0,%1,%2,%3}, [%4];"
                 : "=r"(r[0]), "=r"(r[1]), "=r"(r[2]), "=r"(r[3]) : "r"(a));
}
__device__ __forceinline__ void ldm_x4t(uint32_t a, uint32_t* r)
{
    asm volatile("ldmatrix.sync.aligned.m8n8.x4.trans.shared.b16 {%0,%1,%2,%3}, [%4];"
                 : "=r"(r[0]), "=r"(r[1]), "=r"(r[2]), "=r"(r[3]) : "r"(a));
}
__device__ __forceinline__ void mma_fp16(float* c, const uint32_t* a,
                                         const uint32_t* b)
{
    asm volatile(
        "mma.sync.aligned.m16n8k16.row.col.f32.f16.f16.f32 "
        "{%0,%1,%2,%3}, {%4,%5,%6,%7}, {%8,%9}, {%0,%1,%2,%3};"
        : "+f"(c[0]), "+f"(c[1]), "+f"(c[2]), "+f"(c[3])
        : "r"(a[0]), "r"(a[1]), "r"(a[2]), "r"(a[3]), "r"(b[0]), "r"(b[1]));
}
__device__ __forceinline__ uint32_t pack2h(float a, float b)
{
    __half2 t = __floats2half2_rn(a, b);
    return *(uint32_t*)&t;
}
__device__ __forceinline__ float ex2f(float x)
{
    float r; asm("ex2.approx.f32 %0, %1;" : "=f"(r) : "f"(x)); return r;
}
__device__ __forceinline__ uint32_t hex2(uint32_t x)
{
    uint32_t r; asm("ex2.approx.f16x2 %0, %1;" : "=r"(r) : "r"(x)); return r;
}
__device__ __forceinline__ uint32_t hmul2u(uint32_t a, uint32_t f)
{
    __half2 r = __hmul2(*(__half2*)&a, *(__half2*)&f);
    return *(uint32_t*)&r;
}

__global__ __launch_bounds__(NTHR, 2)
void fa14_kernel(float* __restrict__ out)
{
    extern __shared__ __align__(16) unsigned char smraw[];
    uint32_t sb = (uint32_t)__cvta_generic_to_shared(smraw);

    const int tid  = threadIdx.x;
    const int lane = tid & 31;
    const int w    = tid >> 5;          // 4 warps; rows 16w.. and 64+16w..
    const int bh   = blockIdx.y;
    const int qb   = blockIdx.x;

    const size_t kvbase = (size_t)bh * SEQ * HD;

    auto tile_ld = [&](uint32_t dstb, const char* srcb) {
        #pragma unroll
        for (int i = 0; i < 8; i++) {
            int c = tid + i * NTHR;
            cp16(dstb + swz(c >> 3, c & 7),
                 srcb + ((size_t)(c >> 3) * HD + (c & 7) * 8) * 2);
        }
    };
    auto load_K = [&](int i) {
        tile_ld(sb + O_K0 + (i % 3) * 16384,
                (const char*)g_k + (kvbase + (size_t)i * BN * HD) * 2);
    };
    auto load_V = [&](int i) {
        tile_ld(sb + O_V0 + (i % 3) * 16384,
                (const char*)g_v + (kvbase + (size_t)i * BN * HD) * 2);
    };

    // ---- prologue: Q (128x64 = 16KB) staged through V slot 2 ----
    {
        const char* qp = (const char*)(g_q + ((size_t)bh * SEQ + (size_t)qb * BM) * HD);
        #pragma unroll
        for (int i = 0; i < 8; i++) {
            int c = tid + i * NTHR;
            cp16(sb + O_V0 + 2 * 16384 + swz(c >> 3, c & 7),
                 qp + ((size_t)(c >> 3) * HD + (c & 7) * 8) * 2);
        }
    }
    load_K(0); load_V(0);
    cp_commit();                                // g0 = {Q, K0, V0}
    load_K(1); load_V(1);
    cp_commit();                                // g1 = {K1, V1}

    cp_wait1();                                 // g0 done
    __syncthreads();

    // ---- persistent Q fragments for both row-groups ----
    uint32_t qfA[4][4], qfB[4][4];
    {
        int quad = lane >> 3, i = lane & 7;
        int rowA = w * 16 + (quad & 1) * 8 + i;
        #pragma unroll
        for (int t = 0; t < 4; t++) {
            ldm_x4(sb + O_V0 + 2 * 16384 + swz(rowA,      2 * t + (quad >> 1)), qfA[t]);
            ldm_x4(sb + O_V0 + 2 * 16384 + swz(rowA + 64, 2 * t + (quad >> 1)), qfB[t]);
        }
    }

    float oA[8][4], oB[8][4];
    #pragma unroll
    for (int n = 0; n < 8; n++)
        #pragma unroll
        for (int r = 0; r < 4; r++) { oA[n][r] = 0.f; oB[n][r] = 0.f; }
    float osA[4] = {0.f, 0.f, 0.f, 0.f};
    float osB[4] = {0.f, 0.f, 0.f, 0.f};
    float mrA0 = -1e30f, mrA1 = -1e30f, mrB0 = -1e30f, mrB1 = -1e30f;
    const uint32_t bones[2] = {ONES2, ONES2};

    const int rowKB = (lane & 7) + ((lane >> 4) << 3);
    const int chB   = (lane >> 3) & 1;
    const int vri   = lane & 15;
    const int vch   = lane >> 4;

    for (int blk = 0; blk < NBLK; blk++) {
        if (blk) cp_wait1();                    // K/V(blk) arrived
        __syncthreads();                        // + all warps done with blk-1
        // (sync also orders the Q ldmatrix reads before slot-2 overwrite)

        if (blk + 2 < NBLK) { load_K(blk + 2); load_V(blk + 2); }
        cp_commit();                            // one group per iter, always

        uint32_t kh_b = sb + O_K0 + (blk % 3) * 16384;
        uint32_t vh_b = sb + O_V0 + (blk % 3) * 16384;

        uint32_t ppA[32], ppB[32];
        float bmA0, bmA1, bmB0, bmB1;

        // ===== group A pass: quarter-wise QK + exp (c regs die per quarter) =====
        {
            float qm0[4], qm1[4];
            #pragma unroll
            for (int qi = 0; qi < 4; qi++) {
                float c[4][4];
                #pragma unroll
                for (int j = 0; j < 4; j++)
                    #pragma unroll
                    for (int r = 0; r < 4; r++) c[j][r] = 0.f;
                #pragma unroll
                for (int j2 = 0; j2 < 2; j2++) {
                    int row = 32 * qi + 16 * j2 + rowKB;
                    #pragma unroll
                    for (int t = 0; t < 4; t++) {
                        uint32_t b4[4];
                        ldm_x4(kh_b + swz(row, 2 * t + chB), b4);
                        mma_fp16(c[2*j2],   qfA[t], b4);
                        mma_fp16(c[2*j2+1], qfA[t], b4 + 2);
                    }
                }
                float a0 = -1e30f, a1 = -1e30f;
                #pragma unroll
                for (int j = 0; j < 4; j++) {
                    a0 = fmaxf(a0, fmaxf(c[j][0], c[j][1]));
                    a1 = fmaxf(a1, fmaxf(c[j][2], c[j][3]));
                }
                a0 = fmaxf(a0, __shfl_xor_sync(0xffffffffu, a0, 1));
                a0 = fmaxf(a0, __shfl_xor_sync(0xffffffffu, a0, 2));
                a1 = fmaxf(a1, __shfl_xor_sync(0xffffffffu, a1, 1));
                a1 = fmaxf(a1, __shfl_xor_sync(0xffffffffu, a1, 2));
                qm0[qi] = a0; qm1[qi] = a1;
                #pragma unroll
                for (int j = 0; j < 4; j++) {
                    ppA[8*qi+2*j]   = hex2(pack2h(c[j][0] - a0, c[j][1] - a0));
                    ppA[8*qi+2*j+1] = hex2(pack2h(c[j][2] - a1, c[j][3] - a1));
                }
            }
            bmA0 = fmaxf(fmaxf(qm0[0], qm0[1]), fmaxf(qm0[2], qm0[3]));
            bmA1 = fmaxf(fmaxf(qm1[0], qm1[1]), fmaxf(qm1[2], qm1[3]));
            #pragma unroll
            for (int qi = 0; qi < 4; qi++) {
                if (__ballot_sync(0xffffffffu,
                        (qm0[qi] < bmA0) || (qm1[qi] < bmA1))) {
                    float f0 = ex2f(qm0[qi] - bmA0), f1 = ex2f(qm1[qi] - bmA1);
                    uint32_t u0 = pack2h(f0, f0), u1 = pack2h(f1, f1);
                    #pragma unroll
                    for (int j = 0; j < 4; j++) {
                        ppA[8*qi+2*j]   = hmul2u(ppA[8*qi+2*j],   u0);
                        ppA[8*qi+2*j+1] = hmul2u(ppA[8*qi+2*j+1], u1);
                    }
                }
            }
        }

        // ===== group B pass (reloads K quarter fragments; cA regs reused) =====
        {
            float qm0[4], qm1[4];
            #pragma unroll
            for (int qi = 0; qi < 4; qi++) {
                float c[4][4];
                #pragma unroll
                for (int j = 0; j < 4; j++)
                    #pragma unroll
                    for (int r = 0; r < 4; r++) c[j][r] = 0.f;
                #pragma unroll
                for (int j2 = 0; j2 < 2; j2++) {
                    int row = 32 * qi + 16 * j2 + rowKB;
                    #pragma unroll
                    for (int t = 0; t < 4; t++) {
                        uint32_t b4[4];
                        ldm_x4(kh_b + swz(row, 2 * t + chB), b4);
                        mma_fp16(c[2*j2],   qfB[t], b4);
                        mma_fp16(c[2*j2+1], qfB[t], b4 + 2);
                    }
                }
                float a0 = -1e30f, a1 = -1e30f;
                #pragma unroll
                for (int j = 0; j < 4; j++) {
                    a0 = fmaxf(a0, fmaxf(c[j][0], c[j][1]));
                    a1 = fmaxf(a1, fmaxf(c[j][2], c[j][3]));
                }
                a0 = fmaxf(a0, __shfl_xor_sync(0xffffffffu, a0, 1));
                a0 = fmaxf(a0, __shfl_xor_sync(0xffffffffu, a0, 2));
                a1 = fmaxf(a1, __shfl_xor_sync(0xffffffffu, a1, 1));
                a1 = fmaxf(a1, __shfl_xor_sync(0xffffffffu, a1, 2));
                qm0[qi] = a0; qm1[qi] = a1;
                #pragma unroll
                for (int j = 0; j < 4; j++) {
                    ppB[8*qi+2*j]   = hex2(pack2h(c[j][0] - a0, c[j][1] - a0));
                    ppB[8*qi+2*j+1] = hex2(pack2h(c[j][2] - a1, c[j][3] - a1));
                }
            }
            bmB0 = fmaxf(fmaxf(qm0[0], qm0[1]), fmaxf(qm0[2], qm0[3]));
            bmB1 = fmaxf(fmaxf(qm1[0], qm1[1]), fmaxf(qm1[2], qm1[3]));
            #pragma unroll
            for (int qi = 0; qi < 4; qi++) {
                if (__ballot_sync(0xffffffffu,
                        (qm0[qi] < bmB0) || (qm1[qi] < bmB1))) {
                    float f0 = ex2f(qm0[qi] - bmB0), f1 = ex2f(qm1[qi] - bmB1);
                    uint32_t u0 = pack2h(f0, f0), u1 = pack2h(f1, f1);
                    #pragma unroll
                    for (int j = 0; j < 4; j++) {
                        ppB[8*qi+2*j]   = hmul2u(ppB[8*qi+2*j],   u0);
                        ppB[8*qi+2*j+1] = hmul2u(ppB[8*qi+2*j+1], u1);
                    }
                }
            }
        }

        // ---- rescale O/osum (vote-skip; e==1 exactly when no new max) ----
        if (__ballot_sync(0xffffffffu, (bmA0 > mrA0) || (bmA1 > mrA1) ||
                                       (bmB0 > mrB0) || (bmB1 > mrB1))) {
            float nA0 = fmaxf(mrA0, bmA0), nA1 = fmaxf(mrA1, bmA1);
            float nB0 = fmaxf(mrB0, bmB0), nB1 = fmaxf(mrB1, bmB1);
            float eA0 = ex2f(mrA0 - nA0), eA1 = ex2f(mrA1 - nA1);
            float eB0 = ex2f(mrB0 - nB0), eB1 = ex2f(mrB1 - nB1);
            mrA0 = nA0; mrA1 = nA1; mrB0 = nB0; mrB1 = nB1;
            #pragma unroll
            for (int n = 0; n < 8; n++) {
                oA[n][0] *= eA0; oA[n][1] *= eA0;
                oA[n][2] *= eA1; oA[n][3] *= eA1;
                oB[n][0] *= eB0; oB[n][1] *= eB0;
                oB[n][2] *= eB1; oB[n][3] *= eB1;
            }
            osA[0] *= eA0; osA[1] *= eA0; osA[2] *= eA1; osA[3] *= eA1;
            osB[0] *= eB0; osB[1] *= eB0; osB[2] *= eB1; osB[3] *= eB1;
        }

        // ---- PV: each V fragment feeds 4 MMAs (groups A and B) ----
        #pragma unroll
        for (int t = 0; t < 8; t++) {
            int vrow = 16 * t + vri;
            #pragma unroll
            for (int np = 0; np < 4; np++) {
                uint32_t v4[4];
                ldm_x4t(vh_b + swz(vrow, 2 * np + vch), v4);
                mma_fp16(oA[2*np],   ppA + 4*t, v4);
                mma_fp16(oA[2*np+1], ppA + 4*t, v4 + 2);
                mma_fp16(oB[2*np],   ppB + 4*t, v4);
                mma_fp16(oB[2*np+1], ppB + 4*t, v4 + 2);
            }
            mma_fp16(osA, ppA + 4*t, bones);
            mma_fp16(osB, ppB + 4*t, bones);
        }
    }

    // ---- epilogue ----
    float iA0 = 1.f / (osA[0] + 1e-6f), iA1 = 1.f / (osA[2] + 1e-6f);
    float iB0 = 1.f / (osB[0] + 1e-6f), iB1 = 1.f / (osB[2] + 1e-6f);
    int r  = lane >> 2;
    int cb = (lane & 3) * 2;
    float* ogA0 = out + ((size_t)bh * SEQ + (size_t)qb * BM + w * 16 + r) * HD;
    float* ogA1 = ogA0 + 8 * HD;
    float* ogB0 = ogA0 + 64 * HD;
    float* ogB1 = ogB0 + 8 * HD;
    #pragma unroll
    for (int n = 0; n < 8; n++) {
        *(float2*)(ogA0 + n * 8 + cb) = make_float2(oA[n][0] * iA0, oA[n][1] * iA0);
        *(float2*)(ogA1 + n * 8 + cb) = make_float2(oA[n][2] * iA1, oA[n][3] * iA1);
        *(float2*)(ogB0 + n * 8 + cb) = make_float2(oB[n][0] * iB0, oB[n][1] * iB0);
        *(float2*)(ogB1 + n * 8 + cb) = make_float2(oB[n][2] * iB1, oB[n][3] * iB1);
    }
}

extern "C" void kernel_launch(void* const* d_in, const int* in_sizes, int n_in,
                              void* d_out, int out_size)
{
    const float* q = (const float*)d_in[0];
    const float* k = (const float*)d_in[1];
    const float* v = (const float*)d_in[2];
    float* o = (float*)d_out;

    int n_bh = in_sizes[0] / (SEQ * HD);    // 32

    cudaFuncSetAttribute(fa14_kernel, cudaFuncAttributeMaxDynamicSharedMemorySize,
                         SMEM_BYTES);

    cvt_kernel<<<(NTOT / 4 + 511) / 512, 512>>>(q, k, v);
    dim3 grid(SEQ / BM, n_bh);
    fa14_kernel<<<grid, NTHR, SMEM_BYTES>>>(o);
}

// round 16
// speedup vs baseline: 1.2392x; 1.2392x over previous
#include <cuda_runtime.h>
#include <cuda_fp16.h>
#include <cstdint>

// FlashAttention B=2,H=16,S=4096,D=64 fp32, non-causal.
// Reference's exact recurrence (block_max variant), BN=128 fixed, in order.
// fa11 base (best: 403.8us) + explicit LDSM double-buffering in QK/PV loops
// + strength-reduced slot indices. Numerically bit-identical to fa11.
// BM=64 / 128 threads / 96KB smem -> 2 CTAs/SM.

#define SEQ   4096
#define HD    64
#define BM    64
#define BN    128
#define NTHR  128
#define NBLK  (SEQ / BN)
#define SCL2E 0.18033688011112042f   // (1/8)*log2(e)
#define ONES2 0x3C003C00u            // half2(1,1)

#define NTOT  (2 * 16 * SEQ * HD)

__device__ __half g_q[NTOT];
__device__ __half g_k[NTOT];
__device__ __half g_v[NTOT];

// ---------------- converter ----------------
__global__ __launch_bounds__(512)
void cvt_kernel(const float* __restrict__ q,
                const float* __restrict__ k,
                const float* __restrict__ v)
{
    int i = blockIdx.x * blockDim.x + threadIdx.x;
    if (i >= NTOT / 4) return;

    float4 tq = ((const float4*)q)[i];
    __half2 qa = __floats2half2_rn(tq.x * SCL2E, tq.y * SCL2E);
    __half2 qb = __floats2half2_rn(tq.z * SCL2E, tq.w * SCL2E);
    *(uint2*)(g_q + 4 * i) = make_uint2(*(uint32_t*)&qa, *(uint32_t*)&qb);

    float4 tk = ((const float4*)k)[i];
    __half2 ka = __floats2half2_rn(tk.x, tk.y);
    __half2 kb = __floats2half2_rn(tk.z, tk.w);
    *(uint2*)(g_k + 4 * i) = make_uint2(*(uint32_t*)&ka, *(uint32_t*)&kb);

    float4 tv = ((const float4*)v)[i];
    __half2 va = __floats2half2_rn(tv.x, tv.y);
    __half2 vb = __floats2half2_rn(tv.z, tv.w);
    *(uint2*)(g_v + 4 * i) = make_uint2(*(uint32_t*)&va, *(uint32_t*)&vb);
}

// ---------------- smem layout (byte offsets) ----------------
// K slots: 0, 16384, 32768.  V slots: 49152, 65536, 81920.
#define O_K0   0
#define O_V0   49152
#define SMEM_BYTES 98304      // 96KB -> 2 CTAs/SM

__device__ __forceinline__ uint32_t swz(uint32_t row, uint32_t ch)
{
    return (row * 8u + (ch ^ (row & 7u))) * 16u;
}

__device__ __forceinline__ void cp16(uint32_t dst, const void* src)
{
    asm volatile("cp.async.cg.shared.global [%0], [%1], 16;" :: "r"(dst), "l"(src));
}
__device__ __forceinline__ void cp_commit() { asm volatile("cp.async.commit_group;"); }
__device__ __forceinline__ void cp_wait1()  { asm volatile("cp.async.wait_group 1;"); }

__device__ __forceinline__ void ldm_x4(uint32_t a, uint32_t* r)
{
    asm volatile("ldmatrix.sync.aligned.m8n8.x4.shared.b16 {%0,%1,%2,%3}, [%4];"
                 : "=r"(r[0]), "=r"(r[1]), "=r"(r[2]), "=r"(r[3]) : "r"(a));
}
__device__ __forceinline__ void ldm_x4t(uint32_t a, uint32_t* r)
{
    asm volatile("ldmatrix.sync.aligned.m8n8.x4.trans.shared.b16 {%0,%1,%2,%3}, [%4];"
                 : "=r"(r[0]), "=r"(r[1]), "=r"(r[2]), "=r"(r[3]) : "r"(a));
}
__device__ __forceinline__ void mma_fp16(float* c, const uint32_t* a,
                                         const uint32_t* b)
{
    asm volatile(
        "mma.sync.aligned.m16n8k16.row.col.f32.f16.f16.f32 "
        "{%0,%1,%2,%3}, {%4,%5,%6,%7}, {%8,%9}, {%0,%1,%2,%3};"
        : "+f"(c[0]), "+f"(c[1]), "+f"(c[2]), "+f"(c[3])
        : "r"(a[0]), "r"(a[1]), "r"(a[2]), "r"(a[3]), "r"(b[0]), "r"(b[1]));
}
__device__ __forceinline__ uint32_t pack2h(float a, float b)
{
    __half2 t = __floats2half2_rn(a, b);
    return *(uint32_t*)&t;
}
__device__ __forceinline__ float ex2f(float x)
{
    float r; asm("ex2.approx.f32 %0, %1;" : "=f"(r) : "f"(x)); return r;
}
__device__ __forceinline__ uint32_t hex2(uint32_t x)
{
    uint32_t r; asm("ex2.approx.f16x2 %0, %1;" : "=r"(r) : "r"(x)); return r;
}

__global__ __launch_bounds__(NTHR, 2)
void fa15_kernel(float* __restrict__ out)
{
    extern __shared__ __align__(16) unsigned char smraw[];
    uint32_t sb = (uint32_t)__cvta_generic_to_shared(smraw);

    const int tid  = threadIdx.x;
    const int lane = tid & 31;
    const int w    = tid >> 5;          // 4 warps, rows w*16..w*16+15
    const int bh   = blockIdx.y;
    const int qb   = blockIdx.x;

    const size_t kvbase = (size_t)bh * SEQ * HD;

    auto tile_ld = [&](uint32_t dstb, const char* srcb) {
        #pragma unroll
        for (int i = 0; i < 8; i++) {           // 1024 chunks (16KB tile)
            int c = tid + i * NTHR;
            cp16(dstb + swz(c >> 3, c & 7),
                 srcb + ((size_t)(c >> 3) * HD + (c & 7) * 8) * 2);
        }
    };
    auto load_K = [&](int i, int slot) {
        tile_ld(sb + O_K0 + slot * 16384,
                (const char*)g_k + (kvbase + (size_t)i * BN * HD) * 2);
    };
    auto load_V = [&](int i, int slot) {
        tile_ld(sb + O_V0 + slot * 16384,
                (const char*)g_v + (kvbase + (size_t)i * BN * HD) * 2);
    };

    // ---- prologue: Q staged through V slot 2 ----
    {
        const char* qp = (const char*)(g_q + ((size_t)bh * SEQ + (size_t)qb * BM) * HD);
        #pragma unroll
        for (int i = 0; i < 4; i++) {           // 512 chunks (Q tile 8KB)
            int c = tid + i * NTHR;
            cp16(sb + O_V0 + 2 * 16384 + swz(c >> 3, c & 7),
                 qp + ((size_t)(c >> 3) * HD + (c & 7) * 8) * 2);
        }
    }
    load_K(0, 0); load_V(0, 0);
    cp_commit();                                // g0 = {Q, K0, V0}
    load_K(1, 1); load_V(1, 1);
    cp_commit();                                // g1 = {K1, V1}

    cp_wait1();                                 // g0 done
    __syncthreads();

    // ---- persistent Q fragments (from V slot 2) ----
    uint32_t qf[4][4];
    {
        int quad = lane >> 3, i = lane & 7;
        int row = w * 16 + (quad & 1) * 8 + i;
        #pragma unroll
        for (int t = 0; t < 4; t++)
            ldm_x4(sb + O_V0 + 2 * 16384 + swz(row, 2 * t + (quad >> 1)), qf[t]);
    }

    float o[8][4];
    #pragma unroll
    for (int n = 0; n < 8; n++)
        #pragma unroll
        for (int r = 0; r < 4; r++) o[n][r] = 0.f;
    float osum[4] = {0.f, 0.f, 0.f, 0.f};       // rowsum via ones-MMA
    float m0 = -1e30f, m1 = -1e30f;
    const uint32_t bones[2] = {ONES2, ONES2};

    const int rowB = (lane & 7) + ((lane >> 4) << 3);
    const int chB  = (lane >> 3) & 1;
    const int vri  = lane & 15;
    const int vch  = lane >> 4;

    int sl_cur = 0;                             // blk % 3
    int sl_pre = 2;                             // (blk+2) % 3

    for (int blk = 0; blk < NBLK; blk++) {
        if (blk) cp_wait1();                    // K/V(blk) arrived
        __syncthreads();                        // + all warps done with blk-1
        // (sync also orders the Q ldmatrix reads before slot-2 overwrite)

        uint32_t kh_b = sb + O_K0 + sl_cur * 16384;
        uint32_t vh_b = sb + O_V0 + sl_cur * 16384;

        // ---- QK^T with explicit LDSM double-buffer ----
        float c[16][4];
        uint32_t fA[4], fB[4];
        ldm_x4(kh_b + swz(rowB, chB), fA);      // fragment (j2=0, t=0)
        #pragma unroll
        for (int j2 = 0; j2 < 8; j2++) {
            c[2*j2][0] = c[2*j2][1] = c[2*j2][2] = c[2*j2][3] = 0.f;
            c[2*j2+1][0] = c[2*j2+1][1] = c[2*j2+1][2] = c[2*j2+1][3] = 0.f;
            #pragma unroll
            for (int t = 0; t < 4; t++) {
                const int idx = j2 * 4 + t;
                uint32_t* cur = (idx & 1) ? fB : fA;
                uint32_t* nxt = (idx & 1) ? fA : fB;
                if (idx + 1 < 32) {
                    int nt = (t + 1) & 3;
                    int nj = j2 + (t == 3);
                    ldm_x4(kh_b + swz(16 * nj + rowB, 2 * nt + chB), nxt);
                }
                mma_fp16(c[2*j2],   qf[t], cur);
                mma_fp16(c[2*j2+1], qf[t], cur + 2);
            }
        }

        // ---- prefetch blk+2 (slots freed by the top sync) ----
        if (blk + 2 < NBLK) { load_K(blk + 2, sl_pre); load_V(blk + 2, sl_pre); }
        cp_commit();                            // one group per iter, always

        // ---- block max (reference recurrence, log2 domain) ----
        float mx0 = -1e30f, mx1 = -1e30f;
        #pragma unroll
        for (int j = 0; j < 16; j++) {
            mx0 = fmaxf(mx0, fmaxf(c[j][0], c[j][1]));
            mx1 = fmaxf(mx1, fmaxf(c[j][2], c[j][3]));
        }
        mx0 = fmaxf(mx0, __shfl_xor_sync(0xffffffffu, mx0, 1));
        mx0 = fmaxf(mx0, __shfl_xor_sync(0xffffffffu, mx0, 2));
        mx1 = fmaxf(mx1, __shfl_xor_sync(0xffffffffu, mx1, 1));
        mx1 = fmaxf(mx1, __shfl_xor_sync(0xffffffffu, mx1, 2));

        // vote-skip rescale: e==2^0==1 exactly when no new max in the warp.
        if (__ballot_sync(0xffffffffu, (mx0 > m0) || (mx1 > m1))) {
            float nm0 = fmaxf(m0, mx0), nm1 = fmaxf(m1, mx1);
            float e0 = ex2f(m0 - nm0), e1 = ex2f(m1 - nm1);
            m0 = nm0; m1 = nm1;
            #pragma unroll
            for (int n = 0; n < 8; n++) {
                o[n][0] *= e0; o[n][1] *= e0;
                o[n][2] *= e1; o[n][3] *= e1;
            }
            osum[0] *= e0; osum[1] *= e0;
            osum[2] *= e1; osum[3] *= e1;
        }

        // ---- chunked pack + f16x2 exp + PV with V-LDSM double-buffer ----
        uint32_t vA[4], vB[4];
        ldm_x4t(vh_b + swz(vri, vch), vA);      // fragment (t=0, np=0)
        #pragma unroll
        for (int t = 0; t < 8; t++) {
            uint32_t pah[4];
            #pragma unroll
            for (int h = 0; h < 2; h++) {
                int j = 2 * t + h;
                pah[2*h]   = hex2(pack2h(c[j][0] - mx0, c[j][1] - mx0));
                pah[2*h+1] = hex2(pack2h(c[j][2] - mx1, c[j][3] - mx1));
            }
            #pragma unroll
            for (int np = 0; np < 4; np++) {
                const int idx = t * 4 + np;
                uint32_t* cur = (idx & 1) ? vB : vA;
                uint32_t* nxt = (idx & 1) ? vA : vB;
                if (idx + 1 < 32) {
                    int nn = (np + 1) & 3;
                    int ntt = t + (np == 3);
                    ldm_x4t(vh_b + swz(16 * ntt + vri, 2 * nn + vch), nxt);
                }
                mma_fp16(o[2*np],   pah, cur);
                mma_fp16(o[2*np+1], pah, cur + 2);
            }
            mma_fp16(osum, pah, bones);          // rowsum column
        }

        sl_cur = (sl_cur == 2) ? 0 : sl_cur + 1;
        sl_pre = (sl_pre == 2) ? 0 : sl_pre + 1;
    }

    // ---- epilogue: osum[0]=rowsum(r), osum[2]=rowsum(r+8) ----
    float inv0 = 1.f / (osum[0] + 1e-6f);
    float inv1 = 1.f / (osum[2] + 1e-6f);
    int r  = lane >> 2;
    int cb = (lane & 3) * 2;
    float* og0 = out + ((size_t)bh * SEQ + (size_t)qb * BM + w * 16 + r) * HD;
    float* og1 = og0 + 8 * HD;
    #pragma unroll
    for (int n = 0; n < 8; n++) {
        *(float2*)(og0 + n * 8 + cb) = make_float2(o[n][0] * inv0, o[n][1] * inv0);
        *(float2*)(og1 + n * 8 + cb) = make_float2(o[n][2] * inv1, o[n][3] * inv1);
    }
}

extern "C" void kernel_launch(void* const* d_in, const int* in_sizes, int n_in,
                              void* d_out, int out_size)
{
    const float* q = (const float*)d_in[0];
    const float* k = (const float*)d_in[1];
    const float* v = (const float*)d_in[2];
    float* o = (float*)d_out;

    int n_bh = in_sizes[0] / (SEQ * HD);    // 32

    cudaFuncSetAttribute(fa15_kernel, cudaFuncAttributeMaxDynamicSharedMemorySize,
                         SMEM_BYTES);

    cvt_kernel<<<(NTOT / 4 + 511) / 512, 512>>>(q, k, v);
    dim3 grid(SEQ / BM, n_bh);
    fa15_kernel<<<grid, NTHR, SMEM_BYTES>>>(o);
}